// round 2
// baseline (speedup 1.0000x reference)
#include <cuda_runtime.h>

// Problem constants
#define NN 256
#define TT 1500
#define NSEG 15           // time segments
#define SEG 100           // steps per segment (15*100 = 1500)
#define CHUNK 25          // smem-staged steps per flush (100 = 4*25)
#define PAD 26            // smem row stride

// p[s][t][n] = 0.075 * g_max[s][n] * clip(u_s[n][t],0,1), transposed [t][n]
__device__ float g_pT[2][TT * NN];
// checkpoints: v after (s+1)*SEG steps, s = 0..13
__device__ float g_chk[NSEG - 1][NN * NN];

__global__ void prep_kernel(const float* __restrict__ u0,
                            const float* __restrict__ u1,
                            const float* __restrict__ ksyn) {
    int idx = blockIdx.x * blockDim.x + threadIdx.x;
    if (idx >= 2 * NN * TT) return;
    int s = idx / (NN * TT);
    int r = idx - s * (NN * TT);
    int n = r / TT;
    int t = r - n * TT;
    const float* u = s ? u1 : u0;
    float k  = ksyn[s * NN + n];
    float gm = k / (20.0f - 2.0f * k);        // num/(e_syn_delta - 2*num)
    float a  = u[n * TT + t];
    a = fminf(fmaxf(a, 0.0f), 1.0f);
    g_pT[s][t * NN + n] = 0.075f * gm * a;    // fold DT*0.75 factor
}

// Checkpoint pass: scan 1400 steps per cell, store v at each segment boundary.
// Identical arithmetic order to the main scan -> bitwise-identical v.
__global__ __launch_bounds__(256) void chk_kernel() {
    const int tid = threadIdx.x;
    const int i = blockIdx.y * 16 + (tid >> 4);
    const int j = blockIdx.x * 16 + (tid & 15);
    const int cell = i * NN + j;

    const float* __restrict__ p0 = g_pT[0];
    const float* __restrict__ p1 = g_pT[1];

    float v = 0.0f;
    for (int s = 0; s < NSEG - 1; s++) {
        const int tb = s * SEG;
        #pragma unroll 25
        for (int k = 0; k < SEG; k++) {
            const int t = tb + k;
            float sg = p0[t * NN + i] + p1[t * NN + j];
            v = fmaf(v, 0.625f - sg, 20.0f * sg);
        }
        g_chk[s][cell] = v;
    }
}

// Main pass: block = (16x16 cell tile, time segment). 100 steps from checkpoint,
// staged in smem 25 at a time, flushed with coalesced warp stores.
__global__ __launch_bounds__(256) void sim_kernel(float* __restrict__ out) {
    __shared__ float buf[256 * PAD];

    const int tid  = threadIdx.x;
    const int tx   = tid & 15;
    const int ty   = tid >> 4;
    const int lane = tid & 31;
    const int wid  = tid >> 5;

    const int seg = blockIdx.z;
    const int i = blockIdx.y * 16 + ty;
    const int j = blockIdx.x * 16 + tx;
    const int cell = i * NN + j;
    const int cellBase = (blockIdx.y * 16) * NN + blockIdx.x * 16;

    const float* __restrict__ p0 = g_pT[0];
    const float* __restrict__ p1 = g_pT[1];

    float v = (seg == 0) ? 0.0f : g_chk[seg - 1][cell];
    const int tseg = seg * SEG;

    for (int c0 = 0; c0 < SEG; c0 += CHUNK) {
        #pragma unroll
        for (int k = 0; k < CHUNK; k++) {
            const int t = tseg + c0 + k;
            float sg = p0[t * NN + i] + p1[t * NN + j];
            v = fmaf(v, 0.625f - sg, 20.0f * sg);
            buf[tid * PAD + k] = v;
        }
        __syncthreads();

        if (lane < CHUNK) {
            #pragma unroll
            for (int c = 0; c < 32; c++) {
                const int bc = wid * 32 + c;                  // block-local cell
                const float val = buf[bc * PAD + lane];
                const int g = cellBase + (bc >> 4) * NN + (bc & 15);
                out[g * TT + tseg + c0 + lane] = val;
            }
        }
        __syncthreads();
    }
}

extern "C" void kernel_launch(void* const* d_in, const int* in_sizes, int n_in,
                              void* d_out, int out_size) {
    const float* u0   = (const float*)d_in[0];   // u_pre_0 (N,T)
    const float* u1   = (const float*)d_in[1];   // u_pre_1 (N,T)
    const float* ksyn = (const float*)d_in[2];   // k_syn (2,N)
    float* out = (float*)d_out;                  // (N,N,T) fp32

    const int prep_total = 2 * NN * TT;
    prep_kernel<<<(prep_total + 255) / 256, 256>>>(u0, u1, ksyn);

    dim3 gridA(NN / 16, NN / 16);
    chk_kernel<<<gridA, 256>>>();

    dim3 gridB(NN / 16, NN / 16, NSEG);
    sim_kernel<<<gridB, 256>>>(out);
}

// round 3
// speedup vs baseline: 1.4084x; 1.4084x over previous
#include <cuda_runtime.h>

// Problem constants
#define NN 256
#define TT 1500
#define NSEG 15           // time segments
#define SEG 100           // stored steps per segment
#define WARM 48           // burn-in steps (0.625^48 ~ 1.6e-10 relative)
#define CHUNK 25          // smem-staged steps per flush (100 = 4*25)
#define PAD 26            // smem row stride

// p[s][t][n] = 0.075 * g_max[s][n] * clip(u_s[n][t],0,1), transposed [t][n]
__device__ float g_pT[2][TT * NN];

// Transposing prep: read u[n][t] coalesced, write pT[t][n] coalesced.
// Grid: (t-tiles, n-tiles, s). 32x32 tiles, 32x8 threads.
__global__ __launch_bounds__(256) void prep_kernel(const float* __restrict__ u0,
                                                   const float* __restrict__ u1,
                                                   const float* __restrict__ ksyn) {
    __shared__ float tile[32][33];
    const int s = blockIdx.z;
    const float* __restrict__ u = s ? u1 : u0;

    const int tBase = blockIdx.x * 32;
    const int nBase = blockIdx.y * 32;
    const int tx = threadIdx.x;          // 0..31
    const int ty = threadIdx.y;          // 0..7

    // load: rows = n, cols = t (coalesced over t)
    #pragma unroll
    for (int r = 0; r < 32; r += 8) {
        const int n = nBase + ty + r;
        const int t = tBase + tx;
        float val = 0.0f;
        if (t < TT) val = u[n * TT + t];
        val = fminf(fmaxf(val, 0.0f), 1.0f);
        tile[ty + r][tx] = val;
    }
    __syncthreads();

    // store: rows = t, cols = n (coalesced over n); scale by per-n factor
    #pragma unroll
    for (int r = 0; r < 32; r += 8) {
        const int t = tBase + ty + r;
        const int n = nBase + tx;
        if (t < TT) {
            float k = ksyn[s * NN + n];
            float gm = k / (20.0f - 2.0f * k);      // num/(e_syn_delta - 2*num)
            g_pT[s][t * NN + n] = 0.075f * gm * tile[tx][ty + r];
        }
    }
}

// Main pass: block = (16x16 cell tile, time segment). Burn-in WARM steps from
// v=0 (contraction makes this exact to ~1e-10), then SEG stored steps, staged
// in smem CHUNK at a time and flushed with coalesced warp stores.
__global__ __launch_bounds__(256) void sim_kernel(float* __restrict__ out) {
    __shared__ float buf[256 * PAD];

    const int tid  = threadIdx.x;
    const int lane = tid & 31;
    const int wid  = tid >> 5;

    const int seg = blockIdx.z;
    const int i = blockIdx.y * 16 + (tid >> 4);
    const int j = blockIdx.x * 16 + (tid & 15);
    const int cellBase = (blockIdx.y * 16) * NN + blockIdx.x * 16;

    const float* __restrict__ p0 = g_pT[0];
    const float* __restrict__ p1 = g_pT[1];

    const int tseg = seg * SEG;
    float v = 0.0f;

    // burn-in (seg 0 starts exactly at v0 = E_REST = 0, no warmup needed)
    if (seg > 0) {
        const int tw = tseg - WARM;
        #pragma unroll 8
        for (int k = 0; k < WARM; k++) {
            const int t = tw + k;
            float sg = p0[t * NN + i] + p1[t * NN + j];
            v = fmaf(v, 0.625f - sg, 20.0f * sg);
        }
    }

    for (int c0 = 0; c0 < SEG; c0 += CHUNK) {
        #pragma unroll
        for (int k = 0; k < CHUNK; k++) {
            const int t = tseg + c0 + k;
            float sg = p0[t * NN + i] + p1[t * NN + j];
            v = fmaf(v, 0.625f - sg, 20.0f * sg);
            buf[tid * PAD + k] = v;
        }
        __syncthreads();

        if (lane < CHUNK) {
            #pragma unroll
            for (int c = 0; c < 32; c++) {
                const int bc = wid * 32 + c;                  // block-local cell
                const float val = buf[bc * PAD + lane];
                const int g = cellBase + (bc >> 4) * NN + (bc & 15);
                out[g * TT + tseg + c0 + lane] = val;
            }
        }
        __syncthreads();
    }
}

extern "C" void kernel_launch(void* const* d_in, const int* in_sizes, int n_in,
                              void* d_out, int out_size) {
    const float* u0   = (const float*)d_in[0];   // u_pre_0 (N,T)
    const float* u1   = (const float*)d_in[1];   // u_pre_1 (N,T)
    const float* ksyn = (const float*)d_in[2];   // k_syn (2,N)
    float* out = (float*)d_out;                  // (N,N,T) fp32

    dim3 gridP((TT + 31) / 32, NN / 32, 2);
    prep_kernel<<<gridP, dim3(32, 8)>>>(u0, u1, ksyn);

    dim3 gridB(NN / 16, NN / 16, NSEG);
    sim_kernel<<<gridB, 256>>>(out);
}

// round 4
// speedup vs baseline: 2.6569x; 1.8865x over previous
#include <cuda_runtime.h>

#define NN 256
#define TT 1500
#define R 4                    // timesteps per lane per chunk
#define CT (32 * R)            // 128 timesteps per warp-chunk
#define NCHUNK ((TT + CT - 1) / CT)   // 12 (11 full + tail of 92 = 23 lanes * 4)

// Single fused kernel. Step collapses to v' = v*(0.625 - s) + 20*s with
// s = gi*sat(u0[i][t]) + gj*sat(u1[j][t]),  gX = 0.075*k/(20-2k).
// Affine maps over t are composed with a warp-level inclusive scan:
// each lane composes R=4 consecutive steps serially, 5 shfl levels compose
// across lanes, then each lane replays its 4 steps from its exclusive prefix.
__global__ __launch_bounds__(512) void sim_kernel(
    const float* __restrict__ u0, const float* __restrict__ u1,
    const float* __restrict__ ksyn, float* __restrict__ out)
{
    const int lane = threadIdx.x & 31;
    const int w    = threadIdx.x >> 5;      // 0..15
    const int i = blockIdx.y * 4 + (w >> 2);
    const int j = blockIdx.x * 4 + (w & 3);

    const float k0 = ksyn[i];
    const float k1 = ksyn[NN + j];
    const float gi = 0.075f * k0 / (20.0f - 2.0f * k0);
    const float gj = 0.075f * k1 / (20.0f - 2.0f * k1);

    const float* __restrict__ r0 = u0 + i * TT;
    const float* __restrict__ r1 = u1 + j * TT;
    float* __restrict__ o = out + (i * NN + j) * TT;

    float carry = 0.0f;                      // v0 = E_REST = 0

    for (int c = 0; c < NCHUNK; c++) {
        const int t = c * CT + lane * R;
        const bool act = (t < TT);           // TT % R == 0 -> whole-lane granularity

        float a0, a1, a2, a3, b0, b1, b2, b3;
        float A, B;
        if (act) {
            float4 x0 = *(const float4*)(r0 + t);
            float4 x1 = *(const float4*)(r1 + t);
            float s;
            s = fmaf(gi, __saturatef(x0.x), gj * __saturatef(x1.x)); a0 = 0.625f - s; b0 = 20.0f * s;
            s = fmaf(gi, __saturatef(x0.y), gj * __saturatef(x1.y)); a1 = 0.625f - s; b1 = 20.0f * s;
            s = fmaf(gi, __saturatef(x0.z), gj * __saturatef(x1.z)); a2 = 0.625f - s; b2 = 20.0f * s;
            s = fmaf(gi, __saturatef(x0.w), gj * __saturatef(x1.w)); a3 = 0.625f - s; b3 = 20.0f * s;
            // local composition of 4 affine maps
            A = a0; B = b0;
            B = fmaf(B, a1, b1); A *= a1;
            B = fmaf(B, a2, b2); A *= a2;
            B = fmaf(B, a3, b3); A *= a3;
        } else {
            A = 1.0f; B = 0.0f;              // identity for tail lanes
            a0 = a1 = a2 = a3 = 1.0f; b0 = b1 = b2 = b3 = 0.0f;
        }

        // inclusive scan of affine maps across lanes:
        // combine with predecessor (Au,Bu): B = A*Bu + B, A = A*Au
        #pragma unroll
        for (int d = 1; d < 32; d <<= 1) {
            float Au = __shfl_up_sync(0xffffffffu, A, d);
            float Bu = __shfl_up_sync(0xffffffffu, B, d);
            if (lane >= d) { B = fmaf(A, Bu, B); A *= Au; }
        }

        // exclusive prefix = inclusive prefix of lane-1
        float Ae = __shfl_up_sync(0xffffffffu, A, 1);
        float Be = __shfl_up_sync(0xffffffffu, B, 1);
        if (lane == 0) { Ae = 1.0f; Be = 0.0f; }
        float v = fmaf(Ae, carry, Be);       // v entering this lane's 4 steps

        // carry across chunks from lane 31's inclusive prefix
        float Al = __shfl_sync(0xffffffffu, A, 31);
        float Bl = __shfl_sync(0xffffffffu, B, 31);
        carry = fmaf(Al, carry, Bl);

        if (act) {
            float4 r;
            v = fmaf(v, a0, b0); r.x = v;
            v = fmaf(v, a1, b1); r.y = v;
            v = fmaf(v, a2, b2); r.z = v;
            v = fmaf(v, a3, b3); r.w = v;
            *(float4*)(o + t) = r;
        }
    }
}

extern "C" void kernel_launch(void* const* d_in, const int* in_sizes, int n_in,
                              void* d_out, int out_size) {
    const float* u0   = (const float*)d_in[0];   // u_pre_0 (N,T)
    const float* u1   = (const float*)d_in[1];   // u_pre_1 (N,T)
    const float* ksyn = (const float*)d_in[2];   // k_syn (2,N)
    float* out = (float*)d_out;                  // (N,N,T) fp32

    dim3 grid(NN / 4, NN / 4);                   // 64 x 64 blocks
    sim_kernel<<<grid, 512>>>(u0, u1, ksyn, out);
}

// round 5
// speedup vs baseline: 2.7866x; 1.0488x over previous
#include <cuda_runtime.h>

#define NN 256
#define TT 1500
#define R 4
#define CT (32 * R)                 // 128 steps per warp-chunk
#define NCHUNK ((TT + CT - 1) / CT) // 12 (tail chunk: lanes 0..22 active, whole lanes)

// q[s][n][t] = 0.3125 - 0.075*g_max[s][n]*sat(u_s[n][t]); a_ij(t) = q0+q1
__device__ float g_q[2][NN * TT];

__global__ __launch_bounds__(256) void prep_kernel(const float* __restrict__ u0,
                                                   const float* __restrict__ u1,
                                                   const float* __restrict__ ksyn) {
    int idx = blockIdx.x * 256 + threadIdx.x;
    if (idx >= NN * TT) return;
    int n = idx / TT;
    float k0 = ksyn[n];
    float c0 = 0.075f * k0 / (20.0f - 2.0f * k0);
    g_q[0][idx] = 0.3125f - c0 * __saturatef(u0[idx]);
    float k1 = ksyn[NN + n];
    float c1 = 0.075f * k1 / (20.0f - 2.0f * k1);
    g_q[1][idx] = 0.3125f - c1 * __saturatef(u1[idx]);
}

// Warp-parallel affine scan: v' = a*v + b, a = q0+q1, b = 12.5 - 20a.
// Lane composes 4 steps locally, TRUNCATED 4-level shfl scan (contraction
// a^4 <= 0.1526 makes >15-lane-old terms < 5e-13), replay from exclusive prefix.
__global__ __launch_bounds__(512) void sim_kernel(float* __restrict__ out) {
    const int lane = threadIdx.x & 31;
    const int w    = threadIdx.x >> 5;      // 0..15
    const int i = blockIdx.y * 4 + (w >> 2);
    const int j = blockIdx.x * 4 + (w & 3);

    const float* __restrict__ q0 = g_q[0] + i * TT;
    const float* __restrict__ q1 = g_q[1] + j * TT;
    float* __restrict__ o = out + (i * NN + j) * TT;

    float carry = 0.0f;                      // v0 = E_REST = 0

    for (int c = 0; c < NCHUNK; c++) {
        const int t = c * CT + lane * R;
        const bool act = (t < TT);

        float a0, a1, a2, a3, b0, b1, b2, b3, A, B;
        if (act) {
            float4 x = *(const float4*)(q0 + t);
            float4 y = *(const float4*)(q1 + t);
            a0 = x.x + y.x;  b0 = fmaf(-20.0f, a0, 12.5f);
            a1 = x.y + y.y;  b1 = fmaf(-20.0f, a1, 12.5f);
            a2 = x.z + y.z;  b2 = fmaf(-20.0f, a2, 12.5f);
            a3 = x.w + y.w;  b3 = fmaf(-20.0f, a3, 12.5f);
            // local composition of 4 affine maps
            A = a0; B = b0;
            B = fmaf(a1, B, b1); A *= a1;
            B = fmaf(a2, B, b2); A *= a2;
            B = fmaf(a3, B, b3); A *= a3;
        } else {
            A = 1.0f; B = 0.0f;
            a0 = a1 = a2 = a3 = 1.0f; b0 = b1 = b2 = b3 = 0.0f;
        }

        // truncated inclusive scan (4 levels, window = 16 lanes = 64 steps)
        #pragma unroll
        for (int d = 1; d <= 8; d <<= 1) {
            float Au = __shfl_up_sync(0xffffffffu, A, d);
            float Bu = __shfl_up_sync(0xffffffffu, B, d);
            if (lane >= d) { B = fmaf(A, Bu, B); A *= Au; }
        }

        // exclusive prefix = inclusive of lane-1; lane 0 = chunk carry
        float Ae = __shfl_up_sync(0xffffffffu, A, 1);
        float Be = __shfl_up_sync(0xffffffffu, B, 1);
        float v = (lane == 0) ? carry : fmaf(Ae, carry, Be);

        // carry across chunks from lane 31 (window covers 64 steps back)
        float Al = __shfl_sync(0xffffffffu, A, 31);
        float Bl = __shfl_sync(0xffffffffu, B, 31);
        carry = fmaf(Al, carry, Bl);

        if (act) {
            float4 r;
            v = fmaf(a0, v, b0); r.x = v;
            v = fmaf(a1, v, b1); r.y = v;
            v = fmaf(a2, v, b2); r.z = v;
            v = fmaf(a3, v, b3); r.w = v;
            *(float4*)(o + t) = r;
        }
    }
}

extern "C" void kernel_launch(void* const* d_in, const int* in_sizes, int n_in,
                              void* d_out, int out_size) {
    const float* u0   = (const float*)d_in[0];   // u_pre_0 (N,T)
    const float* u1   = (const float*)d_in[1];   // u_pre_1 (N,T)
    const float* ksyn = (const float*)d_in[2];   // k_syn (2,N)
    float* out = (float*)d_out;                  // (N,N,T) fp32

    prep_kernel<<<(NN * TT + 255) / 256, 256>>>(u0, u1, ksyn);

    dim3 grid(NN / 4, NN / 4);                   // 64 x 64 blocks, 512 thr
    sim_kernel<<<grid, 512>>>(out);
}